// round 16
// baseline (speedup 1.0000x reference)
#include <cuda_runtime.h>
#include <cuda_bf16.h>
#include <math.h>
#include <stdint.h>

typedef unsigned long long u64;
typedef unsigned int u32;

// Problem constants
#define NB 2048     // queries
#define NS 16384    // supports
#define ND 512      // dim
#define NC 17       // classes
#define KTOP 8
#define KCAND 16    // candidates rescored exactly
#define TAU 10.0f
#define EPS 1e-12f

#define GITERS 8          // ND / 64
#define ASTAGE 16384      // 128 rows x 128B
#define BSTAGE 32768      // 256 rows x 128B
#define GSTAGE (ASTAGE + BSTAGE)
#define GEMM_SMEM (3 * GSTAGE)   // 144 KB, 3-stage
#define NTC 128           // NS / 128 column tiles per row
#define NPART 512         // centroid partial chunks
#define NRED1 16          // stage-1 reduce groups (512/32)

// ---------------- scratch (device globals; no runtime alloc) ----------------
__device__ float g_zn[NB * ND];            // normalized z (fp32, exact)
__device__ float g_sn[NS * ND];            // normalized supports (fp32, exact)
__device__ float g_XX[NB];                 // sum(zn^2) per row
__device__ float g_YY[NS];                 // sum(sn^2) per support
__device__ float g_cent[NC * ND];
__device__ float g_centn[NC * ND];
__device__ float g_cnt[NC];
__device__ int   g_labcls[NS];
__device__ float g_part[NPART * NC * ND];
__device__ float g_part2[NRED1 * NC * ND];
__device__ __align__(16) __nv_bfloat16 g_Ah[NB * ND];   // bf16(zn)
__device__ __align__(16) __nv_bfloat16 g_Bh[NS * ND];   // bf16(sn)
__device__ u64 g_cand[(size_t)NB * NTC * 4];            // per-128col-tile top-4 (8 MB)

// ---------------- PTX helpers ----------------
__device__ __forceinline__ uint32_t smem_u32(const void* p) {
    uint32_t a;
    asm("{ .reg .u64 t; cvta.to.shared.u64 t, %1; cvt.u32.u64 %0, t; }" : "=r"(a) : "l"(p));
    return a;
}
__device__ __forceinline__ void cp16(uint32_t saddr, const void* g) {
    asm volatile("cp.async.cg.shared.global [%0], [%1], 16;" :: "r"(saddr), "l"(g));
}
#define CP_COMMIT() asm volatile("cp.async.commit_group;" ::: "memory")

__device__ __forceinline__ void ldsm4(uint32_t* r, uint32_t addr) {
    asm volatile("ldmatrix.sync.aligned.m8n8.x4.shared.b16 {%0,%1,%2,%3}, [%4];"
        : "=r"(r[0]), "=r"(r[1]), "=r"(r[2]), "=r"(r[3]) : "r"(addr));
}
__device__ __forceinline__ void mma16816(float* d, const uint32_t* a, const uint32_t* b) {
    asm volatile(
        "mma.sync.aligned.m16n8k16.row.col.f32.bf16.bf16.f32 "
        "{%0,%1,%2,%3}, {%4,%5,%6,%7}, {%8,%9}, {%0,%1,%2,%3};"
        : "+f"(d[0]), "+f"(d[1]), "+f"(d[2]), "+f"(d[3])
        : "r"(a[0]), "r"(a[1]), "r"(a[2]), "r"(a[3]), "r"(b[0]), "r"(b[1]));
}

// monotone float encoding: enc(a) > enc(b) <=> a > b
__device__ __forceinline__ u32 fenc(float x) {
    u32 b = __float_as_uint(x);
    return (b & 0x80000000u) ? ~b : (b | 0x80000000u);
}
__device__ __forceinline__ u64 fpack(float x, u32 col) {
    return ((u64)fenc(x) << 32) | (u64)(0xFFFFFFFFu - col);
}
#define FIDX(p) (0xFFFFFFFFu - (u32)(p))

#define CE(a, b) do { if ((a) < (b)) { u64 _t = (a); (a) = (b); (b) = _t; } } while (0)

// ---------------- normalization + bf16 hi + self-dot (vectorized) ----------------
__global__ void k_normalize(const float* __restrict__ z, const float* __restrict__ sup) {
    int gw = (blockIdx.x * blockDim.x + threadIdx.x) >> 5;
    int lane = threadIdx.x & 31;
    if (gw >= NB + NS) return;
    const float* src;
    float* dst;
    __nv_bfloat16* eh;
    float* selfdot;
    bool isA = gw < NB;
    int r = isA ? gw : gw - NB;
    if (isA) { src = z + (size_t)r * ND; dst = g_zn + (size_t)r * ND; eh = g_Ah + (size_t)r * ND; selfdot = g_XX + r; }
    else     { src = sup + (size_t)r * ND; dst = g_sn + (size_t)r * ND; eh = g_Bh + (size_t)r * ND; selfdot = g_YY + r; }
    float4 v[4];
    float ss = 0.f;
#pragma unroll
    for (int j = 0; j < 4; j++) {
        v[j] = *(const float4*)(src + 4 * (lane + 32 * j));
        ss += v[j].x * v[j].x + v[j].y * v[j].y + v[j].z * v[j].z + v[j].w * v[j].w;
    }
#pragma unroll
    for (int o = 16; o; o >>= 1) ss += __shfl_xor_sync(0xffffffffu, ss, o);
    float inv = 1.f / fmaxf(sqrtf(ss), EPS);
    float nn = 0.f;
#pragma unroll
    for (int j = 0; j < 4; j++) {
        float4 x;
        x.x = v[j].x * inv; x.y = v[j].y * inv;
        x.z = v[j].z * inv; x.w = v[j].w * inv;
        nn += x.x * x.x + x.y * x.y + x.z * x.z + x.w * x.w;
        int e = 4 * (lane + 32 * j);
        *(float4*)(dst + e) = x;
        __nv_bfloat162 p0 = __floats2bfloat162_rn(x.x, x.y);
        __nv_bfloat162 p1 = __floats2bfloat162_rn(x.z, x.w);
        u64 pk = ((u64)*(u32*)&p1 << 32) | *(u32*)&p0;
        *(u64*)(eh + e) = pk;
    }
#pragma unroll
    for (int o = 16; o; o >>= 1) nn += __shfl_xor_sync(0xffffffffu, nn, o);
    if (lane == 0) *selfdot = nn;
}

// ---------------- fused: label argmax (blocks 0..63) + column sums (blocks 64..80) ----
__global__ void k_labels(const float* __restrict__ labels) {
    if (blockIdx.x < 64) {
        int n = blockIdx.x * 256 + threadIdx.x;
        const float* r = labels + n * NC;
        float m = r[0]; int mi = 0;
#pragma unroll
        for (int c = 1; c < NC; c++) { float x = r[c]; if (x > m) { m = x; mi = c; } }
        g_labcls[n] = mi;
    } else {
        __shared__ float sh[256];
        int c = blockIdx.x - 64, tid = threadIdx.x;
        float s = 0.f;
        for (int n = tid; n < NS; n += 256) s += labels[n * NC + c];
        sh[tid] = s;
        __syncthreads();
        for (int st = 128; st; st >>= 1) {
            if (tid < st) sh[tid] += sh[tid + st];
            __syncthreads();
        }
        if (tid == 0) g_cnt[c] = sh[0];
    }
}

// ---------------- centroid partials (atomic-free) ----------------
__global__ void k_cent_part(const float* __restrict__ sup) {
    __shared__ float sp[NC * ND];
    int tid = threadIdx.x;
    for (int i = tid; i < NC * ND; i += 512) sp[i] = 0.f;
    __syncthreads();
    int n0 = blockIdx.x * 32;
    for (int n = 0; n < 32; n++) {
        int c = g_labcls[n0 + n];
        sp[c * ND + tid] += sup[(size_t)(n0 + n) * ND + tid];
    }
    __syncthreads();
    float* dst = g_part + (size_t)blockIdx.x * NC * ND;
    for (int i = tid; i < NC * ND; i += 512) dst[i] = sp[i];
}

// ---- split-k reduce ----
__global__ void k_cent_reduce1() {
    int i = blockIdx.x * 256 + threadIdx.x;
    if (i >= NC * ND) return;
    int grp = blockIdx.y;
    float s = 0.f;
#pragma unroll 8
    for (int b = grp * 32; b < (grp + 1) * 32; b++)
        s += g_part[(size_t)b * NC * ND + i];
    g_part2[(size_t)grp * NC * ND + i] = s;
}

__global__ void k_cent_reduce2() {
    int i = blockIdx.x * 256 + threadIdx.x;
    if (i >= NC * ND) return;
    float s = 0.f;
#pragma unroll
    for (int b = 0; b < NRED1; b++) s += g_part2[(size_t)b * NC * ND + i];
    int c = i / ND;
    g_cent[i] = s / (g_cnt[c] + EPS);
}

__global__ void k_cent_norm() {
    int w = threadIdx.x >> 5, lane = threadIdx.x & 31;
    if (w >= NC) return;
    float v[16];
    float ss = 0.f;
#pragma unroll
    for (int i = 0; i < 16; i++) {
        float x = g_cent[w * ND + lane + 32 * i];
        v[i] = x; ss += x * x;
    }
#pragma unroll
    for (int o = 16; o; o >>= 1) ss += __shfl_xor_sync(0xffffffffu, ss, o);
    float inv = 1.f / fmaxf(sqrtf(ss), EPS);
#pragma unroll
    for (int i = 0; i < 16; i++) g_centn[w * ND + lane + 32 * i] = v[i] * inv;
}

// ---------- HMMA GEMM 128x256 tile, 512 threads; top-4 per 128-col tile ----------
// y-split: brow0 selects the row half (0 or 8 blocks of 128).
__global__ __launch_bounds__(512, 1) void k_gemm_mma(int brow0) {
    extern __shared__ __align__(1024) char smem[];
    uint32_t sb = smem_u32(smem);
    const int tid = threadIdx.x;
    const int brow = (brow0 + blockIdx.y) * 128;
    const int bcol = blockIdx.x * 256;
    const int w = tid >> 5, lane = tid & 31;
    const int wm = (w >> 2) * 32;   // 4 warps in m (32 rows each)
    const int wn = (w & 3) * 64;    // 4 warps in n (64 cols each)

    const int lr = tid >> 3, lsg = tid & 7;
    const u32 ldoff = (u32)(lr * 128 + ((lsg * 16) ^ ((lr & 7) << 4)));
    const u32 adst = sb + ldoff;
    const u32 bdst = sb + ASTAGE + ldoff;
    const __nv_bfloat16* asrc = g_Ah + (size_t)(brow + lr) * ND + lsg * 8;
    const __nv_bfloat16* bsrc = g_Bh + (size_t)(bcol + lr) * ND + lsg * 8;

    auto load_stage = [&](u32 soff, int k0) {
        cp16(adst + soff, asrc + k0);
        cp16(adst + soff + 8192, asrc + k0 + (size_t)64 * ND);
#pragma unroll
        for (int i = 0; i < 4; i++)
            cp16(bdst + soff + i * 8192, bsrc + k0 + (size_t)i * 64 * ND);
        CP_COMMIT();
    };

    const u32 m16 = ((u32)lane & 1) << 4;
    const u32 m60 = (((u32)lane >> 1) & 3) << 5;
    const u32 ra = (u32)((wm + (lane & 15)) * 128) + ((((u32)lane >> 4) << 4) ^ m16);
    const u32 rb = (u32)(ASTAGE + (wn + (lane & 7) + ((lane >> 4) << 3)) * 128)
                 + (((((u32)lane >> 3) & 1) << 4) ^ m16);

    float acc[2][8][4];
#pragma unroll
    for (int a = 0; a < 2; a++)
#pragma unroll
        for (int b = 0; b < 8; b++)
#pragma unroll
            for (int c = 0; c < 4; c++) acc[a][b][c] = 0.f;

    load_stage(0, 0);
    load_stage(GSTAGE, 64);

    u32 cs_off = 0;
    u32 ls_off = 2 * GSTAGE;
#pragma unroll 1
    for (int it = 0; it < GITERS; it++) {
        if (it < GITERS - 1) asm volatile("cp.async.wait_group 1;" ::: "memory");
        else                 asm volatile("cp.async.wait_group 0;" ::: "memory");
        __syncthreads();

        if (it + 2 < GITERS) {
            load_stage(ls_off, (it + 2) * 64);
            ls_off = (ls_off == 2 * GSTAGE) ? 0 : ls_off + GSTAGE;
        }

        const u32 Ast = sb + cs_off + ra;
        const u32 Bst = sb + cs_off + rb;
#pragma unroll
        for (int ks = 0; ks < 4; ks++) {
            const u32 q = ((u32)(ks * 32)) ^ m60;
            uint32_t af[2][4], bf[4][4];
            u32 aq = Ast + q, bq = Bst + q;
            ldsm4(af[0], aq);
            ldsm4(af[1], aq + 2048);
#pragma unroll
            for (int ntp = 0; ntp < 4; ntp++)
                ldsm4(bf[ntp], bq + ntp * 2048);
#pragma unroll
            for (int mt = 0; mt < 2; mt++)
#pragma unroll
                for (int nt = 0; nt < 8; nt++)
                    mma16816(acc[mt][nt], af[mt], &bf[nt >> 1][(nt & 1) * 2]);
        }
        cs_off = (cs_off == 2 * GSTAGE) ? 0 : cs_off + GSTAGE;
    }

    // ---- epilogue: per-row top-4 in 64-col warp tile -> pair-merge to 128-col ----
    __syncthreads();
    u64* stage = (u64*)smem;
    const int g = lane >> 2;
    const int qt = lane & 3;
    const u32 colbase = (u32)(bcol + wn + qt * 2);
#pragma unroll
    for (int mt = 0; mt < 2; mt++) {
#pragma unroll
        for (int h = 0; h < 2; h++) {
            u64 s0 = 0, s1 = 0, s2 = 0, s3 = 0;
#pragma unroll
            for (int nt = 0; nt < 8; nt++) {
#pragma unroll
                for (int e = 0; e < 2; e++) {
                    u64 p = fpack(acc[mt][nt][h * 2 + e], colbase + nt * 8 + e);
                    if (p > s3) {
                        s3 = p;
                        CE(s2, s3); CE(s1, s2); CE(s0, s1);
                    }
                }
            }
#pragma unroll
            for (int d = 1; d <= 2; d <<= 1) {
                u64 t0 = __shfl_xor_sync(0xffffffffu, s0, d);
                u64 t1 = __shfl_xor_sync(0xffffffffu, s1, d);
                u64 t2 = __shfl_xor_sync(0xffffffffu, s2, d);
                u64 t3 = __shfl_xor_sync(0xffffffffu, s3, d);
                s0 = s0 > t3 ? s0 : t3;
                s1 = s1 > t2 ? s1 : t2;
                s2 = s2 > t1 ? s2 : t1;
                s3 = s3 > t0 ? s3 : t0;
                CE(s0, s2); CE(s1, s3); CE(s0, s1); CE(s2, s3);
            }
            if (qt == 0) {
                u64* sp = stage + ((size_t)(w * 32 + mt * 16 + h * 8 + g) * 4);
                sp[0] = s0; sp[1] = s1; sp[2] = s2; sp[3] = s3;
            }
        }
    }
    __syncthreads();
    if ((w & 1) == 0) {
        int r = lane;
        const u64* pa = stage + ((size_t)(w * 32 + r) * 4);
        const u64* pb = stage + ((size_t)((w + 1) * 32 + r) * 4);
        u64 a0 = pa[0], a1 = pa[1], a2 = pa[2], a3 = pa[3];
        u64 b0 = pb[0], b1 = pb[1], b2 = pb[2], b3 = pb[3];
        u64 c0 = a0 > b3 ? a0 : b3;
        u64 c1 = a1 > b2 ? a1 : b2;
        u64 c2 = a2 > b1 ? a2 : b1;
        u64 c3 = a3 > b0 ? a3 : b0;
        int row = brow + wm + r;
        int tile128 = blockIdx.x * 2 + ((w & 3) >> 1);
        u64* dst = g_cand + ((size_t)row * NTC + tile128) * 4;
        dst[0] = c0; dst[1] = c1; dst[2] = c2; dst[3] = c3;
    }
}

// ------- per-row: 512 cands -> top-16 -> exact rescore + lazy temp-labels ->
//         top-8 -> targets/outputs + fused logits --------------------------------
__global__ __launch_bounds__(256) void k_select(float* __restrict__ out, int row0) {
    __shared__ float zrow[ND];
    __shared__ float scn[NC * ND];
    __shared__ u64 warpwin[8][KCAND];
    __shared__ int widx[KCAND];
    __shared__ float cdist[KCAND];
    __shared__ float csoft[KCAND][NC + 1];   // +1 pad vs bank conflicts
    __shared__ int cpred[KCAND];
    __shared__ int selslot[KTOP];
    __shared__ float st[NC], so[NC], ssum[2];
    const int row = row0 + blockIdx.x;
    const int tid = threadIdx.x;
    const int w = tid >> 5, lane = tid & 31;

    if (tid < ND / 4)
        ((float4*)zrow)[tid] = ((const float4*)(g_zn + (size_t)row * ND))[tid];
    for (int i = tid; i < (NC * ND) / 4; i += 256)
        ((float4*)scn)[i] = ((const float4*)g_centn)[i];

    // warp-local top-16 of its 64 candidates
    const u64* cand = g_cand + (size_t)row * (NTC * 4) + w * 64;
    u64 l0 = cand[lane], l1 = cand[lane + 32];
    CE(l0, l1);
#pragma unroll
    for (int r = 0; r < KCAND; r++) {
        u64 m = l0;
#pragma unroll
        for (int o = 16; o; o >>= 1) {
            u64 p = __shfl_xor_sync(0xffffffffu, m, o);
            if (p > m) m = p;
        }
        if (l0 == m) { l0 = l1; l1 = 0; }
        if (lane == 0) warpwin[w][r] = m;
    }
    __syncthreads();

    // warp 0 merges 8x16 -> global top-16
    if (w == 0) {
        const u64* ww = &warpwin[0][0];
        u64 a0 = ww[lane], a1 = ww[lane + 32], a2 = ww[lane + 64], a3 = ww[lane + 96];
        CE(a0, a1); CE(a2, a3); CE(a0, a2); CE(a1, a3); CE(a1, a2);
#pragma unroll
        for (int r = 0; r < KCAND; r++) {
            u64 m = a0;
#pragma unroll
            for (int o = 16; o; o >>= 1) {
                u64 p = __shfl_xor_sync(0xffffffffu, m, o);
                if (p > m) m = p;
            }
            if (a0 == m) { a0 = a1; a1 = a2; a2 = a3; a3 = 0; }
            if (lane == 0) widx[r] = (int)FIDX(m);
        }
    }
    __syncthreads();

    // rescore + lazy temp-labels: 2 candidates per warp
    {
        float XXr = g_XX[row];
        for (int c = w; c < KCAND; c += 8) {
            int n = widx[c];
            const float* sr = g_sn + (size_t)n * ND;
            float dz = 0.f;
            float ac[NC];
#pragma unroll
            for (int cc = 0; cc < NC; cc++) ac[cc] = 0.f;
#pragma unroll
            for (int j = 0; j < 4; j++) {
                int base = 4 * (lane + 32 * j);
                float4 s4 = *(const float4*)(sr + base);
                const float* zz = zrow + base;
                dz += s4.x * zz[0] + s4.y * zz[1] + s4.z * zz[2] + s4.w * zz[3];
#pragma unroll
                for (int cc = 0; cc < NC; cc++) {
                    const float* ccp = scn + cc * ND + base;
                    ac[cc] += s4.x * ccp[0] + s4.y * ccp[1] + s4.z * ccp[2] + s4.w * ccp[3];
                }
            }
#pragma unroll
            for (int o = 16; o; o >>= 1) {
                dz += __shfl_xor_sync(0xffffffffu, dz, o);
#pragma unroll
                for (int cc = 0; cc < NC; cc++)
                    ac[cc] += __shfl_xor_sync(0xffffffffu, ac[cc], o);
            }
            if (lane == 0) {
                cdist[c] = XXr + g_YY[n] - 2.f * dz;
                float t[NC];
                float m = -1e30f; int mi = 0;
#pragma unroll
                for (int cc = 0; cc < NC; cc++) {
                    t[cc] = TAU * ac[cc];
                    if (t[cc] > m) { m = t[cc]; mi = cc; }
                }
                float s = 0.f;
#pragma unroll
                for (int cc = 0; cc < NC; cc++) { t[cc] = expf(t[cc] - m); s += t[cc]; }
#pragma unroll
                for (int cc = 0; cc < NC; cc++) csoft[c][cc] = t[cc] / s;
                cpred[c] = mi;
            }
        }
    }

    // fused logits: TAU * zrow . centn[c]
    for (int c = w; c < NC; c += 8) {
        const float* cc = scn + c * ND;
        float d = 0.f;
#pragma unroll
        for (int j = 0; j < 4; j++) {
            int base = 4 * (lane + 32 * j);
            float4 c4 = *(const float4*)(cc + base);
            const float* zz = zrow + base;
            d += c4.x * zz[0] + c4.y * zz[1] + c4.z * zz[2] + c4.w * zz[3];
        }
#pragma unroll
        for (int o = 16; o; o >>= 1) d += __shfl_xor_sync(0xffffffffu, d, o);
        if (lane == 0) out[row * NC + c] = TAU * d;
    }
    __syncthreads();

    // select 8 smallest dist (tie -> lower support index); remember slots
    if (tid == 0) {
        unsigned used = 0;
#pragma unroll
        for (int k = 0; k < KTOP; k++) {
            float bd = 1e30f; int bi = -1, bn = 1 << 30;
#pragma unroll
            for (int c = 0; c < KCAND; c++) {
                if (used & (1u << c)) continue;
                float dc = cdist[c]; int nc_ = widx[c];
                if (dc < bd || (dc == bd && nc_ < bn)) { bd = dc; bi = c; bn = nc_; }
            }
            used |= 1u << bi;
            selslot[k] = bi;
        }
    }
    __syncthreads();

    if (tid < NC) {
        float o = 0.f, tg = 0.f;
#pragma unroll
        for (int k = 0; k < KTOP; k++) {
            int s = selslot[k];
            o += csoft[s][tid];
            tg += (cpred[s] == tid) ? 1.f : 0.f;
        }
        st[tid] = tg; so[tid] = o;
    }
    __syncthreads();
    if (tid == 0) {
        float ts = 0.f, os = 0.f;
#pragma unroll
        for (int c = 0; c < NC; c++) { ts += st[c]; os += so[c]; }
        ssum[0] = ts; ssum[1] = os;
    }
    __syncthreads();
    if (tid < NC) {
        out[(size_t)NB * NC + row * NC + tid] = st[tid] / (ssum[0] + EPS);
        out[(size_t)2 * NB * NC + row * NC + tid] = so[tid] / (ssum[1] + EPS);
    }
}

// ---------------- launch (row-split GEMM; select half 0 pipelined on s2) ----------
extern "C" void kernel_launch(void* const* d_in, const int* in_sizes, int n_in,
                              void* d_out, int out_size) {
    const float* z = (const float*)d_in[0];
    const float* supports = (const float*)d_in[1];
    const float* labels = (const float*)d_in[2];
    float* out = (float*)d_out;

    static cudaStream_t s2 = nullptr;
    static cudaEvent_t evFork = nullptr, evG0 = nullptr, evEnd = nullptr;
    if (s2 == nullptr) {
        cudaStreamCreateWithFlags(&s2, cudaStreamNonBlocking);
        cudaEventCreateWithFlags(&evFork, cudaEventDisableTiming);
        cudaEventCreateWithFlags(&evG0, cudaEventDisableTiming);
        cudaEventCreateWithFlags(&evEnd, cudaEventDisableTiming);
    }

    cudaFuncSetAttribute(k_gemm_mma, cudaFuncAttributeMaxDynamicSharedMemorySize,
                         GEMM_SMEM);

    // Fork s2 at t=0: label/centroid chain depends only on raw inputs.
    cudaEventRecord(evFork, 0);
    cudaStreamWaitEvent(s2, evFork, 0);
    k_labels<<<64 + NC, 256, 0, s2>>>(labels);
    k_cent_part<<<NPART, 512, 0, s2>>>(supports);
    {
        dim3 r1((NC * ND + 255) / 256, NRED1);
        k_cent_reduce1<<<r1, 256, 0, s2>>>();
    }
    k_cent_reduce2<<<(NC * ND + 255) / 256, 256, 0, s2>>>();
    k_cent_norm<<<1, NC * 32, 0, s2>>>();

    // Stream 0: normalize -> GEMM halves
    k_normalize<<<(NB + NS) / 8, 256>>>(z, supports);
    dim3 gg(NS / 256, NB / 256);   // 64 x 8 CTAs per half
    k_gemm_mma<<<gg, 512, GEMM_SMEM>>>(0);
    cudaEventRecord(evG0, 0);
    k_gemm_mma<<<gg, 512, GEMM_SMEM>>>(8);

    // s2: select rows 0..1023 after GEMM half 0 (chain already done on s2)
    cudaStreamWaitEvent(s2, evG0, 0);
    k_select<<<NB / 2, 256, 0, s2>>>(out, 0);
    cudaEventRecord(evEnd, s2);

    // Stream 0: select rows 1024..2047, then join s2 for capture completeness
    k_select<<<NB / 2, 256>>>(out, NB / 2);
    cudaStreamWaitEvent(0, evEnd, 0);
}

// round 17
// speedup vs baseline: 1.9584x; 1.9584x over previous
#include <cuda_runtime.h>
#include <cuda_bf16.h>
#include <math.h>
#include <stdint.h>

typedef unsigned long long u64;
typedef unsigned int u32;

// Problem constants
#define NB 2048     // queries
#define NS 16384    // supports
#define ND 512      // dim
#define NC 17       // classes
#define KTOP 8
#define KCAND 16    // candidates rescored exactly
#define TAU 10.0f
#define EPS 1e-12f

#define GITERS 8          // ND / 64
#define ASTAGE 16384      // 128 rows x 128B
#define BSTAGE 32768      // 256 rows x 128B
#define GSTAGE (ASTAGE + BSTAGE)
#define GEMM_SMEM (3 * GSTAGE)   // 144 KB, 3-stage
#define NTC 128           // NS / 128 column tiles per row
#define NPART 512         // centroid partial chunks
#define NRED1 16          // stage-1 reduce groups (512/32)

// ---------------- scratch (device globals; no runtime alloc) ----------------
__device__ float g_zn[NB * ND];            // normalized z (fp32, exact)
__device__ float g_sn[NS * ND];            // normalized supports (fp32, exact)
__device__ float g_XX[NB];                 // sum(zn^2) per row
__device__ float g_YY[NS];                 // sum(sn^2) per support
__device__ float g_cent[NC * ND];
__device__ float g_centn[NC * ND];
__device__ float g_cnt[NC];
__device__ int   g_labcls[NS];
__device__ float g_part[NPART * NC * ND];
__device__ float g_part2[NRED1 * NC * ND];
__device__ __align__(16) __nv_bfloat16 g_Ah[NB * ND];   // bf16(zn)
__device__ __align__(16) __nv_bfloat16 g_Bh[NS * ND];   // bf16(sn)
__device__ u64 g_cand[(size_t)NB * NTC * 4];            // per-128col-tile top-4 (8 MB)

// ---------------- PTX helpers ----------------
__device__ __forceinline__ uint32_t smem_u32(const void* p) {
    uint32_t a;
    asm("{ .reg .u64 t; cvta.to.shared.u64 t, %1; cvt.u32.u64 %0, t; }" : "=r"(a) : "l"(p));
    return a;
}
__device__ __forceinline__ void cp16(uint32_t saddr, const void* g) {
    asm volatile("cp.async.cg.shared.global [%0], [%1], 16;" :: "r"(saddr), "l"(g));
}
#define CP_COMMIT() asm volatile("cp.async.commit_group;" ::: "memory")

__device__ __forceinline__ void ldsm4(uint32_t* r, uint32_t addr) {
    asm volatile("ldmatrix.sync.aligned.m8n8.x4.shared.b16 {%0,%1,%2,%3}, [%4];"
        : "=r"(r[0]), "=r"(r[1]), "=r"(r[2]), "=r"(r[3]) : "r"(addr));
}
__device__ __forceinline__ void mma16816(float* d, const uint32_t* a, const uint32_t* b) {
    asm volatile(
        "mma.sync.aligned.m16n8k16.row.col.f32.bf16.bf16.f32 "
        "{%0,%1,%2,%3}, {%4,%5,%6,%7}, {%8,%9}, {%0,%1,%2,%3};"
        : "+f"(d[0]), "+f"(d[1]), "+f"(d[2]), "+f"(d[3])
        : "r"(a[0]), "r"(a[1]), "r"(a[2]), "r"(a[3]), "r"(b[0]), "r"(b[1]));
}

// monotone float encoding: enc(a) > enc(b) <=> a > b
__device__ __forceinline__ u32 fenc(float x) {
    u32 b = __float_as_uint(x);
    return (b & 0x80000000u) ? ~b : (b | 0x80000000u);
}
__device__ __forceinline__ u64 fpack(float x, u32 col) {
    return ((u64)fenc(x) << 32) | (u64)(0xFFFFFFFFu - col);
}
#define FIDX(p) (0xFFFFFFFFu - (u32)(p))

#define CE(a, b) do { if ((a) < (b)) { u64 _t = (a); (a) = (b); (b) = _t; } } while (0)

// ---------------- normalization + bf16 hi + self-dot (vectorized) ----------------
__global__ void k_normalize(const float* __restrict__ z, const float* __restrict__ sup) {
    int gw = (blockIdx.x * blockDim.x + threadIdx.x) >> 5;
    int lane = threadIdx.x & 31;
    if (gw >= NB + NS) return;
    const float* src;
    float* dst;
    __nv_bfloat16* eh;
    float* selfdot;
    bool isA = gw < NB;
    int r = isA ? gw : gw - NB;
    if (isA) { src = z + (size_t)r * ND; dst = g_zn + (size_t)r * ND; eh = g_Ah + (size_t)r * ND; selfdot = g_XX + r; }
    else     { src = sup + (size_t)r * ND; dst = g_sn + (size_t)r * ND; eh = g_Bh + (size_t)r * ND; selfdot = g_YY + r; }
    float4 v[4];
    float ss = 0.f;
#pragma unroll
    for (int j = 0; j < 4; j++) {
        v[j] = *(const float4*)(src + 4 * (lane + 32 * j));
        ss += v[j].x * v[j].x + v[j].y * v[j].y + v[j].z * v[j].z + v[j].w * v[j].w;
    }
#pragma unroll
    for (int o = 16; o; o >>= 1) ss += __shfl_xor_sync(0xffffffffu, ss, o);
    float inv = 1.f / fmaxf(sqrtf(ss), EPS);
    float nn = 0.f;
#pragma unroll
    for (int j = 0; j < 4; j++) {
        float4 x;
        x.x = v[j].x * inv; x.y = v[j].y * inv;
        x.z = v[j].z * inv; x.w = v[j].w * inv;
        nn += x.x * x.x + x.y * x.y + x.z * x.z + x.w * x.w;
        int e = 4 * (lane + 32 * j);
        *(float4*)(dst + e) = x;
        __nv_bfloat162 p0 = __floats2bfloat162_rn(x.x, x.y);
        __nv_bfloat162 p1 = __floats2bfloat162_rn(x.z, x.w);
        u64 pk = ((u64)*(u32*)&p1 << 32) | *(u32*)&p0;
        *(u64*)(eh + e) = pk;
    }
#pragma unroll
    for (int o = 16; o; o >>= 1) nn += __shfl_xor_sync(0xffffffffu, nn, o);
    if (lane == 0) *selfdot = nn;
}

// ---------------- fused: label argmax (blocks 0..63) + column sums (blocks 64..80) ----
__global__ void k_labels(const float* __restrict__ labels) {
    if (blockIdx.x < 64) {
        int n = blockIdx.x * 256 + threadIdx.x;
        const float* r = labels + n * NC;
        float m = r[0]; int mi = 0;
#pragma unroll
        for (int c = 1; c < NC; c++) { float x = r[c]; if (x > m) { m = x; mi = c; } }
        g_labcls[n] = mi;
    } else {
        __shared__ float sh[256];
        int c = blockIdx.x - 64, tid = threadIdx.x;
        float s = 0.f;
        for (int n = tid; n < NS; n += 256) s += labels[n * NC + c];
        sh[tid] = s;
        __syncthreads();
        for (int st = 128; st; st >>= 1) {
            if (tid < st) sh[tid] += sh[tid + st];
            __syncthreads();
        }
        if (tid == 0) g_cnt[c] = sh[0];
    }
}

// ---------------- centroid partials (atomic-free) ----------------
__global__ void k_cent_part(const float* __restrict__ sup) {
    __shared__ float sp[NC * ND];
    int tid = threadIdx.x;
    for (int i = tid; i < NC * ND; i += 512) sp[i] = 0.f;
    __syncthreads();
    int n0 = blockIdx.x * 32;
    for (int n = 0; n < 32; n++) {
        int c = g_labcls[n0 + n];
        sp[c * ND + tid] += sup[(size_t)(n0 + n) * ND + tid];
    }
    __syncthreads();
    float* dst = g_part + (size_t)blockIdx.x * NC * ND;
    for (int i = tid; i < NC * ND; i += 512) dst[i] = sp[i];
}

// ---- split-k reduce ----
__global__ void k_cent_reduce1() {
    int i = blockIdx.x * 256 + threadIdx.x;
    if (i >= NC * ND) return;
    int grp = blockIdx.y;
    float s = 0.f;
#pragma unroll 8
    for (int b = grp * 32; b < (grp + 1) * 32; b++)
        s += g_part[(size_t)b * NC * ND + i];
    g_part2[(size_t)grp * NC * ND + i] = s;
}

__global__ void k_cent_reduce2() {
    int i = blockIdx.x * 256 + threadIdx.x;
    if (i >= NC * ND) return;
    float s = 0.f;
#pragma unroll
    for (int b = 0; b < NRED1; b++) s += g_part2[(size_t)b * NC * ND + i];
    int c = i / ND;
    g_cent[i] = s / (g_cnt[c] + EPS);
}

__global__ void k_cent_norm() {
    int w = threadIdx.x >> 5, lane = threadIdx.x & 31;
    if (w >= NC) return;
    float v[16];
    float ss = 0.f;
#pragma unroll
    for (int i = 0; i < 16; i++) {
        float x = g_cent[w * ND + lane + 32 * i];
        v[i] = x; ss += x * x;
    }
#pragma unroll
    for (int o = 16; o; o >>= 1) ss += __shfl_xor_sync(0xffffffffu, ss, o);
    float inv = 1.f / fmaxf(sqrtf(ss), EPS);
#pragma unroll
    for (int i = 0; i < 16; i++) g_centn[w * ND + lane + 32 * i] = v[i] * inv;
}

// ---------- HMMA GEMM 128x256 tile, 512 threads; top-4 per 128-col tile ----------
__global__ __launch_bounds__(512, 1) void k_gemm_mma() {
    extern __shared__ __align__(1024) char smem[];
    uint32_t sb = smem_u32(smem);
    const int tid = threadIdx.x;
    const int brow = blockIdx.y * 128;
    const int bcol = blockIdx.x * 256;
    const int w = tid >> 5, lane = tid & 31;
    const int wm = (w >> 2) * 32;   // 4 warps in m (32 rows each)
    const int wn = (w & 3) * 64;    // 4 warps in n (64 cols each)

    const int lr = tid >> 3, lsg = tid & 7;
    const u32 ldoff = (u32)(lr * 128 + ((lsg * 16) ^ ((lr & 7) << 4)));
    const u32 adst = sb + ldoff;
    const u32 bdst = sb + ASTAGE + ldoff;
    const __nv_bfloat16* asrc = g_Ah + (size_t)(brow + lr) * ND + lsg * 8;
    const __nv_bfloat16* bsrc = g_Bh + (size_t)(bcol + lr) * ND + lsg * 8;

    auto load_stage = [&](u32 soff, int k0) {
        cp16(adst + soff, asrc + k0);
        cp16(adst + soff + 8192, asrc + k0 + (size_t)64 * ND);
#pragma unroll
        for (int i = 0; i < 4; i++)
            cp16(bdst + soff + i * 8192, bsrc + k0 + (size_t)i * 64 * ND);
        CP_COMMIT();
    };

    const u32 m16 = ((u32)lane & 1) << 4;
    const u32 m60 = (((u32)lane >> 1) & 3) << 5;
    const u32 ra = (u32)((wm + (lane & 15)) * 128) + ((((u32)lane >> 4) << 4) ^ m16);
    const u32 rb = (u32)(ASTAGE + (wn + (lane & 7) + ((lane >> 4) << 3)) * 128)
                 + (((((u32)lane >> 3) & 1) << 4) ^ m16);

    float acc[2][8][4];
#pragma unroll
    for (int a = 0; a < 2; a++)
#pragma unroll
        for (int b = 0; b < 8; b++)
#pragma unroll
            for (int c = 0; c < 4; c++) acc[a][b][c] = 0.f;

    load_stage(0, 0);
    load_stage(GSTAGE, 64);

    u32 cs_off = 0;
    u32 ls_off = 2 * GSTAGE;
#pragma unroll 1
    for (int it = 0; it < GITERS; it++) {
        if (it < GITERS - 1) asm volatile("cp.async.wait_group 1;" ::: "memory");
        else                 asm volatile("cp.async.wait_group 0;" ::: "memory");
        __syncthreads();

        if (it + 2 < GITERS) {
            load_stage(ls_off, (it + 2) * 64);
            ls_off = (ls_off == 2 * GSTAGE) ? 0 : ls_off + GSTAGE;
        }

        const u32 Ast = sb + cs_off + ra;
        const u32 Bst = sb + cs_off + rb;
#pragma unroll
        for (int ks = 0; ks < 4; ks++) {
            const u32 q = ((u32)(ks * 32)) ^ m60;
            uint32_t af[2][4], bf[4][4];
            u32 aq = Ast + q, bq = Bst + q;
            ldsm4(af[0], aq);
            ldsm4(af[1], aq + 2048);
#pragma unroll
            for (int ntp = 0; ntp < 4; ntp++)
                ldsm4(bf[ntp], bq + ntp * 2048);
#pragma unroll
            for (int mt = 0; mt < 2; mt++)
#pragma unroll
                for (int nt = 0; nt < 8; nt++)
                    mma16816(acc[mt][nt], af[mt], &bf[nt >> 1][(nt & 1) * 2]);
        }
        cs_off = (cs_off == 2 * GSTAGE) ? 0 : cs_off + GSTAGE;
    }

    // ---- epilogue: per-row top-4 in 64-col warp tile -> pair-merge to 128-col ----
    __syncthreads();
    u64* stage = (u64*)smem;
    const int g = lane >> 2;
    const int qt = lane & 3;
    const u32 colbase = (u32)(bcol + wn + qt * 2);
#pragma unroll
    for (int mt = 0; mt < 2; mt++) {
#pragma unroll
        for (int h = 0; h < 2; h++) {
            u64 s0 = 0, s1 = 0, s2 = 0, s3 = 0;
#pragma unroll
            for (int nt = 0; nt < 8; nt++) {
#pragma unroll
                for (int e = 0; e < 2; e++) {
                    u64 p = fpack(acc[mt][nt][h * 2 + e], colbase + nt * 8 + e);
                    if (p > s3) {
                        s3 = p;
                        CE(s2, s3); CE(s1, s2); CE(s0, s1);
                    }
                }
            }
#pragma unroll
            for (int d = 1; d <= 2; d <<= 1) {
                u64 t0 = __shfl_xor_sync(0xffffffffu, s0, d);
                u64 t1 = __shfl_xor_sync(0xffffffffu, s1, d);
                u64 t2 = __shfl_xor_sync(0xffffffffu, s2, d);
                u64 t3 = __shfl_xor_sync(0xffffffffu, s3, d);
                s0 = s0 > t3 ? s0 : t3;
                s1 = s1 > t2 ? s1 : t2;
                s2 = s2 > t1 ? s2 : t1;
                s3 = s3 > t0 ? s3 : t0;
                CE(s0, s2); CE(s1, s3); CE(s0, s1); CE(s2, s3);
            }
            if (qt == 0) {
                u64* sp = stage + ((size_t)(w * 32 + mt * 16 + h * 8 + g) * 4);
                sp[0] = s0; sp[1] = s1; sp[2] = s2; sp[3] = s3;
            }
        }
    }
    __syncthreads();
    if ((w & 1) == 0) {
        int r = lane;
        const u64* pa = stage + ((size_t)(w * 32 + r) * 4);
        const u64* pb = stage + ((size_t)((w + 1) * 32 + r) * 4);
        u64 a0 = pa[0], a1 = pa[1], a2 = pa[2], a3 = pa[3];
        u64 b0 = pb[0], b1 = pb[1], b2 = pb[2], b3 = pb[3];
        u64 c0 = a0 > b3 ? a0 : b3;
        u64 c1 = a1 > b2 ? a1 : b2;
        u64 c2 = a2 > b1 ? a2 : b1;
        u64 c3 = a3 > b0 ? a3 : b0;
        int row = brow + wm + r;
        int tile128 = blockIdx.x * 2 + ((w & 3) >> 1);
        u64* dst = g_cand + ((size_t)row * NTC + tile128) * 4;
        dst[0] = c0; dst[1] = c1; dst[2] = c2; dst[3] = c3;
    }
}

// ------- per-row: 512 cands -> top-16 -> exact rescore -> top-8 ->
//         lazy temp-labels (8 selected only) -> targets/outputs + logits ---------
__global__ __launch_bounds__(256) void k_select(float* __restrict__ out) {
    __shared__ float zrow[ND];
    __shared__ float scn[NC * ND];
    __shared__ u64 warpwin[8][KCAND];
    __shared__ int widx[KCAND];
    __shared__ float cdist[KCAND];
    __shared__ int sel[KTOP];
    __shared__ float soSel[KTOP][NC + 1];
    __shared__ int predSel[KTOP];
    __shared__ float st[NC], so[NC], ssum[2];
    const int row = blockIdx.x;
    const int tid = threadIdx.x;
    const int w = tid >> 5, lane = tid & 31;

    if (tid < ND / 4)
        ((float4*)zrow)[tid] = ((const float4*)(g_zn + (size_t)row * ND))[tid];
    for (int i = tid; i < (NC * ND) / 4; i += 256)
        ((float4*)scn)[i] = ((const float4*)g_centn)[i];

    // warp-local top-16 of its 64 candidates (no block barriers)
    const u64* cand = g_cand + (size_t)row * (NTC * 4) + w * 64;
    u64 l0 = cand[lane], l1 = cand[lane + 32];
    CE(l0, l1);
#pragma unroll
    for (int r = 0; r < KCAND; r++) {
        u64 m = l0;
#pragma unroll
        for (int o = 16; o; o >>= 1) {
            u64 p = __shfl_xor_sync(0xffffffffu, m, o);
            if (p > m) m = p;
        }
        if (l0 == m) { l0 = l1; l1 = 0; }
        if (lane == 0) warpwin[w][r] = m;
    }
    __syncthreads();

    // warp 0 merges 8x16 = 128 entries -> global top-16
    if (w == 0) {
        const u64* ww = &warpwin[0][0];
        u64 a0 = ww[lane], a1 = ww[lane + 32], a2 = ww[lane + 64], a3 = ww[lane + 96];
        CE(a0, a1); CE(a2, a3); CE(a0, a2); CE(a1, a3); CE(a1, a2);
#pragma unroll
        for (int r = 0; r < KCAND; r++) {
            u64 m = a0;
#pragma unroll
            for (int o = 16; o; o >>= 1) {
                u64 p = __shfl_xor_sync(0xffffffffu, m, o);
                if (p > m) m = p;
            }
            if (a0 == m) { a0 = a1; a1 = a2; a2 = a3; a3 = 0; }
            if (lane == 0) widx[r] = (int)FIDX(m);
        }
    }
    __syncthreads();

    // exact fp32 rescore: dist = XX + YY - 2*dot  (2 candidates per warp, float4)
    {
        float XXr = g_XX[row];
        for (int c = w; c < KCAND; c += 8) {
            int n = widx[c];
            const float* sr = g_sn + (size_t)n * ND;
            float d = 0.f;
#pragma unroll
            for (int j = 0; j < 4; j++) {
                int base = 4 * (lane + 32 * j);
                float4 s4 = *(const float4*)(sr + base);
                const float* zz = zrow + base;
                d += s4.x * zz[0] + s4.y * zz[1] + s4.z * zz[2] + s4.w * zz[3];
            }
#pragma unroll
            for (int o = 16; o; o >>= 1) d += __shfl_xor_sync(0xffffffffu, d, o);
            if (lane == 0) cdist[c] = XXr + g_YY[n] - 2.f * d;
        }
    }

    // fused logits: TAU * zrow . centn[c]
    for (int c = w; c < NC; c += 8) {
        const float* cc = scn + c * ND;
        float d = 0.f;
#pragma unroll
        for (int j = 0; j < 4; j++) {
            int base = 4 * (lane + 32 * j);
            float4 c4 = *(const float4*)(cc + base);
            const float* zz = zrow + base;
            d += c4.x * zz[0] + c4.y * zz[1] + c4.z * zz[2] + c4.w * zz[3];
        }
#pragma unroll
        for (int o = 16; o; o >>= 1) d += __shfl_xor_sync(0xffffffffu, d, o);
        if (lane == 0) out[row * NC + c] = TAU * d;
    }
    __syncthreads();

    // select 8 smallest dist (tie -> lower support index)
    if (tid == 0) {
        unsigned used = 0;
#pragma unroll
        for (int k = 0; k < KTOP; k++) {
            float bd = 1e30f; int bi = -1, bn = 1 << 30;
#pragma unroll
            for (int c = 0; c < KCAND; c++) {
                if (used & (1u << c)) continue;
                float dc = cdist[c]; int nc_ = widx[c];
                if (dc < bd || (dc == bd && nc_ < bn)) { bd = dc; bi = c; bn = nc_; }
            }
            used |= 1u << bi;
            sel[k] = bn;
        }
    }
    __syncthreads();

    // lazy temp-labels for the 8 selected supports: warp k handles sel[k].
    // Classes serialized -> one live accumulator; support row preloaded once.
    if (w < KTOP) {
        int n = sel[w];
        const float* sr = g_sn + (size_t)n * ND;
        float4 v[4];
#pragma unroll
        for (int j = 0; j < 4; j++)
            v[j] = *(const float4*)(sr + 4 * (lane + 32 * j));
        float t[NC];
#pragma unroll 1
        for (int c = 0; c < NC; c++) {
            const float* cc = scn + c * ND;
            float d = 0.f;
#pragma unroll
            for (int j = 0; j < 4; j++) {
                int base = 4 * (lane + 32 * j);
                float4 c4 = *(const float4*)(cc + base);
                d += v[j].x * c4.x + v[j].y * c4.y + v[j].z * c4.z + v[j].w * c4.w;
            }
#pragma unroll
            for (int o = 16; o; o >>= 1) d += __shfl_xor_sync(0xffffffffu, d, o);
            t[c] = TAU * d;   // identical on all lanes after butterfly
        }
        float m = -1e30f; int mi = 0;
#pragma unroll
        for (int c = 0; c < NC; c++) if (t[c] > m) { m = t[c]; mi = c; }
        float s = 0.f;
#pragma unroll
        for (int c = 0; c < NC; c++) { t[c] = expf(t[c] - m); s += t[c]; }
        if (lane < NC) soSel[w][lane] = t[lane] / s;
        if (lane == 0) predSel[w] = mi;
    }
    __syncthreads();

    if (tid < NC) {
        float o = 0.f, tg = 0.f;
#pragma unroll
        for (int k = 0; k < KTOP; k++) {
            o += soSel[k][tid];
            tg += (predSel[k] == tid) ? 1.f : 0.f;
        }
        st[tid] = tg; so[tid] = o;
    }
    __syncthreads();
    if (tid == 0) {
        float ts = 0.f, os = 0.f;
#pragma unroll
        for (int c = 0; c < NC; c++) { ts += st[c]; os += so[c]; }
        ssum[0] = ts; ssum[1] = os;
    }
    __syncthreads();
    if (tid < NC) {
        out[(size_t)NB * NC + row * NC + tid] = st[tid] / (ssum[0] + EPS);
        out[(size_t)2 * NB * NC + row * NC + tid] = so[tid] / (ssum[1] + EPS);
    }
}

// ---------------- launch (s2 chain forked at t=0; no post-GEMM join needed) -------
extern "C" void kernel_launch(void* const* d_in, const int* in_sizes, int n_in,
                              void* d_out, int out_size) {
    const float* z = (const float*)d_in[0];
    const float* supports = (const float*)d_in[1];
    const float* labels = (const float*)d_in[2];
    float* out = (float*)d_out;

    static cudaStream_t s2 = nullptr;
    static cudaEvent_t evFork = nullptr, evJoin = nullptr;
    if (s2 == nullptr) {
        cudaStreamCreateWithFlags(&s2, cudaStreamNonBlocking);
        cudaEventCreateWithFlags(&evFork, cudaEventDisableTiming);
        cudaEventCreateWithFlags(&evJoin, cudaEventDisableTiming);
    }

    cudaFuncSetAttribute(k_gemm_mma, cudaFuncAttributeMaxDynamicSharedMemorySize,
                         GEMM_SMEM);

    // Fork s2 at t=0: label/centroid chain depends only on raw inputs.
    cudaEventRecord(evFork, 0);
    cudaStreamWaitEvent(s2, evFork, 0);
    k_labels<<<64 + NC, 256, 0, s2>>>(labels);
    k_cent_part<<<NPART, 512, 0, s2>>>(supports);
    {
        dim3 r1((NC * ND + 255) / 256, NRED1);
        k_cent_reduce1<<<r1, 256, 0, s2>>>();
    }
    k_cent_reduce2<<<(NC * ND + 255) / 256, 256, 0, s2>>>();
    k_cent_norm<<<1, NC * 32, 0, s2>>>();
    cudaEventRecord(evJoin, s2);

    // Stream 0: normalize -> GEMM (s2 chain completes well before GEMM ends)
    k_normalize<<<(NB + NS) / 8, 256>>>(z, supports);
    dim3 gg(NS / 256, NB / 128);
    k_gemm_mma<<<gg, 512, GEMM_SMEM>>>();

    cudaStreamWaitEvent(0, evJoin, 0);
    k_select<<<NB, 256>>>(out);
}